// round 1
// baseline (speedup 1.0000x reference)
#include <cuda_runtime.h>

#define NB 64
#define NP 24564
#define NM 16
#define NC 21
#define RPT 8
#define BLK 256
#define GX ((NP + BLK * RPT - 1) / (BLK * RPT))

// -------- scratch (no allocations allowed) --------
__device__ float g_mined[(size_t)NB * NP];          // mined loss_c (0 for positives)
__device__ unsigned short g_packed[(size_t)NB * NP]; // conf(5b) | bt_idx(4b)<<5 | pos<<9
__device__ unsigned long long g_bpkey[NB * NM];      // per-truth best prior key
__device__ int g_numpos[NB];
__device__ float g_sumpos[NB];                       // sum of loss_c_all over positives
__device__ float g_lossl;
__device__ float g_lossc;

__device__ __forceinline__ float sl1_sum(float tx1, float ty1, float tx2, float ty2,
                                         float px, float py, float pw, float ph,
                                         float4 ld)
{
    // encode (matches reference op order)
    float lt0 = ((tx1 + tx2) * 0.5f - px) / (0.1f * pw);
    float lt1 = ((ty1 + ty2) * 0.5f - py) / (0.1f * ph);
    float lt2 = __logf((tx2 - tx1) / pw) / 0.2f;
    float lt3 = __logf((ty2 - ty1) / ph) / 0.2f;
    float s = 0.f, d, a;
    d = ld.x - lt0; a = fabsf(d); s += (a < 1.f) ? 0.5f * d * d : a - 0.5f;
    d = ld.y - lt1; a = fabsf(d); s += (a < 1.f) ? 0.5f * d * d : a - 0.5f;
    d = ld.z - lt2; a = fabsf(d); s += (a < 1.f) ? 0.5f * d * d : a - 0.5f;
    d = ld.w - lt3; a = fabsf(d); s += (a < 1.f) ? 0.5f * d * d : a - 0.5f;
    return s;
}

__global__ void k_init()
{
    int t = threadIdx.x;
    if (t < NB * NM) g_bpkey[t] = 0ull;
    if (t < NB) { g_numpos[t] = 0; g_sumpos[t] = 0.f; }
    if (t == 0) { g_lossl = 0.f; g_lossc = 0.f; }
}

__global__ void __launch_bounds__(BLK) k_match(const float* __restrict__ loc,
                                               const float* __restrict__ conf,
                                               const float* __restrict__ priors,
                                               const float* __restrict__ targets)
{
    int b = blockIdx.y;
    __shared__ float s_t[NM][6];  // x1,y1,x2,y2,area,label
    __shared__ unsigned long long s_key[NM];
    __shared__ float s_lossl, s_sumpos;
    __shared__ int s_np;
    int tid = threadIdx.x;

    if (tid < NM) {
        const float* tg = targets + ((size_t)b * NM + tid) * 5;
        float x1 = tg[0], y1 = tg[1], x2 = tg[2], y2 = tg[3];
        s_t[tid][0] = x1; s_t[tid][1] = y1; s_t[tid][2] = x2; s_t[tid][3] = y2;
        s_t[tid][4] = (x2 - x1) * (y2 - y1);
        s_t[tid][5] = tg[4];
        s_key[tid] = 0ull;
    }
    if (tid == 0) { s_lossl = 0.f; s_sumpos = 0.f; s_np = 0; }
    __syncthreads();

    float lov[NM];
    int lpi[NM];
#pragma unroll
    for (int j = 0; j < NM; j++) { lov[j] = -1.f; lpi[j] = 0; }

    float t_lossl = 0.f, t_sumpos = 0.f;
    int t_np = 0;

    int base = blockIdx.x * (BLK * RPT) + tid;
    for (int k = 0; k < RPT; k++) {
        int p = base + k * BLK;
        if (p < NP) {
            float4 pr = __ldg((const float4*)priors + p);
            float bx1 = pr.x - pr.z * 0.5f;
            float by1 = pr.y - pr.w * 0.5f;
            float bx2 = pr.x + pr.z * 0.5f;
            float by2 = pr.y + pr.w * 0.5f;
            float area_b = (bx2 - bx1) * (by2 - by1);

            float bov = -1.f;
            int bj = 0;
#pragma unroll
            for (int j = 0; j < NM; j++) {
                float ix1 = fmaxf(s_t[j][0], bx1);
                float iy1 = fmaxf(s_t[j][1], by1);
                float ix2 = fminf(s_t[j][2], bx2);
                float iy2 = fminf(s_t[j][3], by2);
                float iw = fmaxf(ix2 - ix1, 0.f);
                float ih = fmaxf(iy2 - iy1, 0.f);
                float inter = iw * ih;
                float iou = inter / (s_t[j][4] + area_b - inter);
                if (iou > bov) { bov = iou; bj = j; }     // first-max tie rule over j
                if (iou > lov[j]) { lov[j] = iou; lpi[j] = p; } // first-max over p (ascending)
            }

            // fused logsumexp over 21 classes (row in registers)
            const float* cr = conf + ((size_t)b * NP + p) * NC;
            float xv[NC];
#pragma unroll
            for (int c = 0; c < NC; c++) xv[c] = __ldg(cr + c);
            float m = xv[0];
#pragma unroll
            for (int c = 1; c < NC; c++) m = fmaxf(m, xv[c]);
            float es = 0.f;
#pragma unroll
            for (int c = 0; c < NC; c++) es += __expf(xv[c] - m);
            float lse = m + __logf(es);

            int cf = 0;
            bool pos = false;
            if (!(bov < 0.5f)) { cf = (int)(s_t[bj][5] + 1.0f); pos = true; }
            float gath = xv[0];
#pragma unroll
            for (int c = 1; c < NC; c++) if (c == cf) gath = xv[c];
            float lca = lse - gath;

            size_t off = (size_t)b * NP + p;
            if (pos) {
                float4 ld = __ldg((const float4*)loc + off);
                t_lossl += sl1_sum(s_t[bj][0], s_t[bj][1], s_t[bj][2], s_t[bj][3],
                                   pr.x, pr.y, pr.z, pr.w, ld);
                t_sumpos += lca;
                t_np++;
                g_mined[off] = 0.f;
            } else {
                g_mined[off] = lca;
            }
            g_packed[off] = (unsigned short)(cf | (bj << 5) | ((pos ? 1 : 0) << 9));
        }
    }

#pragma unroll
    for (int j = 0; j < NM; j++) {
        if (lov[j] >= 0.f) {
            unsigned long long key =
                ((unsigned long long)__float_as_uint(lov[j]) << 32) |
                (unsigned long long)(0xFFFFFFFFu - (unsigned)lpi[j]);
            atomicMax(&s_key[j], key);
        }
    }
    atomicAdd(&s_lossl, t_lossl);
    atomicAdd(&s_sumpos, t_sumpos);
    atomicAdd(&s_np, t_np);
    __syncthreads();

    if (tid < NM && s_key[tid]) atomicMax(&g_bpkey[b * NM + tid], s_key[tid]);
    if (tid == 0) {
        atomicAdd(&g_lossl, s_lossl);
        atomicAdd(&g_sumpos[b], s_sumpos);
        atomicAdd(&g_numpos[b], s_np);
    }
}

// Sequential per-batch override fixup (last-write-wins on duplicate best-prior indices)
__global__ void k_fix(const float* __restrict__ loc,
                      const float* __restrict__ conf,
                      const float* __restrict__ priors,
                      const float* __restrict__ targets)
{
    int b = threadIdx.x;
    if (b >= NB) return;
    float d_lossl = 0.f;
    for (int j = 0; j < NM; j++) {
        unsigned long long key = g_bpkey[b * NM + j];
        int p = (int)(0xFFFFFFFFu - (unsigned)(key & 0xFFFFFFFFull));
        size_t off = (size_t)b * NP + p;
        const float* cr = conf + off * NC;
        float m = cr[0];
        for (int c = 1; c < NC; c++) m = fmaxf(m, cr[c]);
        float es = 0.f;
        for (int c = 0; c < NC; c++) es += __expf(cr[c] - m);
        float lse = m + __logf(es);

        unsigned us = g_packed[off];
        int cold = us & 31;
        int btold = (us >> 5) & 15;
        bool posold = (us >> 9) & 1;

        const float* tgj = targets + ((size_t)b * NM + j) * 5;
        int cnew = (int)(tgj[4] + 1.0f);
        float lca_new = lse - cr[cnew];
        float4 pr = __ldg((const float4*)priors + p);
        float4 ld = __ldg((const float4*)loc + off);
        float sl_new = sl1_sum(tgj[0], tgj[1], tgj[2], tgj[3],
                               pr.x, pr.y, pr.z, pr.w, ld);
        if (posold) {
            float lca_old = lse - cr[cold];
            const float* tgo = targets + ((size_t)b * NM + btold) * 5;
            float sl_old = sl1_sum(tgo[0], tgo[1], tgo[2], tgo[3],
                                   pr.x, pr.y, pr.z, pr.w, ld);
            g_sumpos[b] += lca_new - lca_old;
            d_lossl += sl_new - sl_old;
        } else {
            g_numpos[b] += 1;
            g_sumpos[b] += lca_new;
            d_lossl += sl_new;
            g_mined[off] = 0.f;
        }
        g_packed[off] = (unsigned short)(cnew | (j << 5) | (1 << 9));
    }
    atomicAdd(&g_lossl, d_lossl);
}

// Per-batch radix select of the K-th largest mined value; sum of selected = S_gt + (K-c_gt)*t*
__global__ void __launch_bounds__(256) k_select()
{
    int b = blockIdx.x;
    __shared__ unsigned cnt[256];
    __shared__ unsigned s_prefix;
    __shared__ unsigned s_krem;
    __shared__ float s_sum;
    __shared__ unsigned s_cgt;
    int tid = threadIdx.x;

    int np = g_numpos[b];
    long long Kl = 3ll * np;
    int K = (Kl < (long long)(NP - 1)) ? (int)Kl : (NP - 1);
    if (K <= 0) {
        if (tid == 0) atomicAdd(&g_lossc, g_sumpos[b]);
        return;
    }
    const float* mb = g_mined + (size_t)b * NP;
    if (tid == 0) { s_prefix = 0u; s_krem = (unsigned)K; s_sum = 0.f; s_cgt = 0u; }

    for (int pass = 0; pass < 4; pass++) {
        int shift = 24 - 8 * pass;
        cnt[tid] = 0;
        __syncthreads();
        unsigned pref = s_prefix;
        for (int i = tid; i < NP; i += 256) {
            unsigned u = __float_as_uint(mb[i]);
            if (((unsigned long long)(u ^ pref) >> (shift + 8)) == 0ull)
                atomicAdd(&cnt[(u >> shift) & 255u], 1u);
        }
        __syncthreads();
        if (tid == 0) {
            unsigned kr = s_krem;
            int d = 255;
            for (;;) {
                if (cnt[d] >= kr) break;
                kr -= cnt[d];
                d--;
            }
            s_prefix = pref | ((unsigned)d << shift);
            s_krem = kr;
        }
        __syncthreads();
    }

    unsigned tb = s_prefix;
    float tval = __uint_as_float(tb);
    float lsum = 0.f;
    unsigned lcnt = 0;
    for (int i = tid; i < NP; i += 256) {
        float v = mb[i];
        if (__float_as_uint(v) > tb) { lsum += v; lcnt++; }
    }
    atomicAdd(&s_sum, lsum);
    atomicAdd(&s_cgt, lcnt);
    __syncthreads();
    if (tid == 0) {
        float lossc_b = g_sumpos[b] + s_sum + (float)(K - (int)s_cgt) * tval;
        atomicAdd(&g_lossc, lossc_b);
    }
}

__global__ void k_final(float* out)
{
    int n = 0;
    for (int b = 0; b < NB; b++) n += g_numpos[b];
    float fn = (float)n;
    out[0] = g_lossl / fn;
    out[1] = g_lossc / fn;
}

extern "C" void kernel_launch(void* const* d_in, const int* in_sizes, int n_in,
                              void* d_out, int out_size)
{
    const float* loc = (const float*)d_in[0];
    const float* conf = (const float*)d_in[1];
    const float* priors = (const float*)d_in[2];
    const float* targets = (const float*)d_in[3];

    k_init<<<1, 1024>>>();
    dim3 g(GX, NB);
    k_match<<<g, BLK>>>(loc, conf, priors, targets);
    k_fix<<<1, NB>>>(loc, conf, priors, targets);
    k_select<<<NB, 256>>>();
    k_final<<<1, 1>>>((float*)d_out);
}